// round 16
// baseline (speedup 1.0000x reference)
#include <cuda_runtime.h>
#include <cuda_fp16.h>
#include <cstdint>

// ---------------------------------------------------------------------------
// SocialPooling: pooled[i] = scatter-add of neighbor hidden states into an
// 8x8 grid around anchor i, then out = relu(pooled @ W + b).
// Fixed instance: S=64, P=64, B=4096, H=64, g2=64 -> K=4096, N=1024.
// Round 15 (= R14 resubmit; infra failure, no measurement): R13 mbarrier
// pipeline + BKF 32->64 (halves wait rounds now that warps are decoupled).
// NST=3, LDAH=72. Pool (linked-list) + fused transpose unchanged.
// ---------------------------------------------------------------------------

#define H_DIM 64
#define G2    64
#define PP    64

#define M_TOT 4096
#define N_TOT 1024
#define K_TOT 4096

#define BM 128
#define BN 128
#define BKF 64                           // fp16 k per chunk (4 k16 steps)
#define NST 3
#define NC (K_TOT / BKF)                 // 64 chunks

#define LDAH 72                          // fp16 row stride (144B), conflict-free
#define A_BYTES (BM * LDAH * 2)          // 18432
#define STAGE_BYTES (2 * BM * LDAH * 2)  // 36864
#define MBAR_OFF (NST * STAGE_BYTES)     // 110592
#define SMEM_GEMM (MBAR_OFF + 64)        // 3 full + 3 empty mbarriers

// prep kernel smem layout
#define PA 8
#define POOL_BLOCKS (M_TOT / PA)          // 512
#define PK_POS  16384
#define PK_HEAD 16896
#define PK_NEXT 18944
#define SMEM_PREP 20992

// scratch: fp16 pooled A (32 MB) + fp16 W^T [N,K] (8 MB)
__device__ __half g_poolh[(size_t)M_TOT * K_TOT];
__device__ __half g_Wth[(size_t)N_TOT * K_TOT];

// ---------------------------------------------------------------------------
// helpers
// ---------------------------------------------------------------------------
__device__ __forceinline__ uint32_t smem_u32(const void* p) {
    uint32_t a;
    asm("{ .reg .u64 t; cvta.to.shared.u64 t, %1; cvt.u32.u64 %0, t; }" : "=r"(a) : "l"(p));
    return a;
}
__device__ __forceinline__ void cp16(uint32_t dst, const void* src) {
    asm volatile("cp.async.cg.shared.global [%0], [%1], 16;" :: "r"(dst), "l"(src));
}
__device__ __forceinline__ void mbar_init(uint32_t m, uint32_t cnt) {
    asm volatile("mbarrier.init.shared.b64 [%0], %1;" :: "r"(m), "r"(cnt) : "memory");
}
__device__ __forceinline__ void cp_mbar_arrive(uint32_t m) {
    asm volatile("cp.async.mbarrier.arrive.noinc.shared.b64 [%0];" :: "r"(m) : "memory");
}
__device__ __forceinline__ void mbar_arrive(uint32_t m) {
    asm volatile("mbarrier.arrive.shared.b64 _, [%0];" :: "r"(m) : "memory");
}
__device__ __forceinline__ void mbar_wait(uint32_t m, uint32_t parity) {
    asm volatile(
        "{\n\t.reg .pred P1;\n\t"
        "LAB_%=:\n\t"
        "mbarrier.try_wait.parity.shared::cta.b64 P1, [%0], %1, 0x989680;\n\t"
        "@P1 bra.uni DONE_%=;\n\t"
        "bra.uni LAB_%=;\n\t"
        "DONE_%=:\n\t}"
        :: "r"(m), "r"(parity) : "memory");
}
__device__ __forceinline__ void ldsm4(uint32_t* r, uint32_t addr) {
    asm volatile("ldmatrix.sync.aligned.m8n8.x4.shared.b16 {%0,%1,%2,%3}, [%4];"
                 : "=r"(r[0]), "=r"(r[1]), "=r"(r[2]), "=r"(r[3]) : "r"(addr));
}
__device__ __forceinline__ void mma16816(float* d, const uint32_t* a,
                                         uint32_t b0, uint32_t b1) {
    asm volatile(
        "mma.sync.aligned.m16n8k16.row.col.f32.f16.f16.f32 "
        "{%0,%1,%2,%3}, {%4,%5,%6,%7}, {%8,%9}, {%0,%1,%2,%3};"
        : "+f"(d[0]), "+f"(d[1]), "+f"(d[2]), "+f"(d[3])
        : "r"(a[0]), "r"(a[1]), "r"(a[2]), "r"(a[3]), "r"(b0), "r"(b1));
}

// ---------------------------------------------------------------------------
// Kernel 1 (fused prep): blocks [0,512) pool, rest transpose W.
// ---------------------------------------------------------------------------
__global__ __launch_bounds__(256) void prep_kernel(
    const float* __restrict__ h_states, const float* __restrict__ end_pos,
    const float* __restrict__ W)
{
    extern __shared__ __align__(16) char sm[];
    const int tid = threadIdx.x;

    if (blockIdx.x < POOL_BLOCKS) {
        float*  sh_hidden = (float*)sm;                 // 4096 f32
        float2* sh_pos    = (float2*)(sm + PK_POS);     // 64
        int*    sh_head   = (int*)(sm + PK_HEAD);       // [PA][64]
        int*    sh_next   = (int*)(sm + PK_NEXT);       // [PA][64]

        const int blk = blockIdx.x;
        const int s  = blk >> 3;
        const int a0 = (blk & 7) * PA;

        const float4* hseq = (const float4*)(h_states + (size_t)s * PP * H_DIM);
        #pragma unroll
        for (int k = tid; k < PP * H_DIM / 4; k += 256)
            ((float4*)sh_hidden)[k] = hseq[k];
        if (tid < PP) sh_pos[tid] = ((const float2*)end_pos)[(size_t)s * PP + tid];
        #pragma unroll
        for (int k = tid; k < PA * 64; k += 256) sh_head[k] = -1;
        __syncthreads();

        #pragma unroll
        for (int idx = tid; idx < PA * 64; idx += 256) {
            int a = idx >> 6, j = idx & 63;
            int p = a0 + a;
            float px = sh_pos[p].x, py = sh_pos[p].y;
            float tlx = px - 1.0f, tly = py + 1.0f;
            float brx = px + 1.0f, bry = py - 1.0f;
            float ox = sh_pos[j].x, oy = sh_pos[j].y;
            bool oob = (ox >= brx) || (ox <= tlx) || (oy >= tly) || (oy <= bry) || (j == p);
            int cx = (int)floorf((ox - tlx) / 2.0f * 8.0f);
            int cy = (int)floorf((tly - oy) / 2.0f * 8.0f);
            int c = cx + cy * 8;
            if (!oob && c >= 0 && c < G2)
                sh_next[idx] = atomicExch(&sh_head[a * 64 + c], j);
        }
        __syncthreads();

        const int w = tid >> 5, l = tid & 31;
        const int h0 = sh_head[w * 64 + l];
        const int h1 = sh_head[w * 64 + 32 + l];
        const int* nx = sh_next + w * 64;
        const float2* hid2 = (const float2*)sh_hidden;
        uint32_t* dst = (uint32_t*)(g_poolh + (size_t)(s * PP + a0 + w) * (G2 * H_DIM));
        #pragma unroll
        for (int c = 0; c < G2; c++) {
            int j = __shfl_sync(0xffffffffu, (c < 32) ? h0 : h1, c & 31);
            uint32_t u = 0u;
            if (j >= 0) {
                float2 acc = hid2[j * 32 + l];
                j = nx[j];
                while (j >= 0) {
                    float2 v = hid2[j * 32 + l];
                    acc.x += v.x; acc.y += v.y;
                    j = nx[j];
                }
                __half2 h = __floats2half2_rn(acc.x, acc.y);
                u = *reinterpret_cast<uint32_t*>(&h);
            }
            dst[c * 32 + l] = u;
        }
    } else {
        float (*tile)[33] = (float(*)[33])sm;
        const int bid = blockIdx.x - POOL_BLOCKS;
        const int n0 = (bid & 31) * 32, k0 = (bid >> 5) * 32;
        const int tx = tid & 31, ty = tid >> 5;
        #pragma unroll
        for (int i = 0; i < 4; i++) {
            int r = ty + i * 8;
            tile[r][tx] = W[(size_t)(k0 + r) * N_TOT + n0 + tx];
        }
        __syncthreads();
        #pragma unroll
        for (int i = 0; i < 4; i++) {
            int r = ty + i * 8;
            g_Wth[(size_t)(n0 + r) * K_TOT + k0 + tx] = __float2half_rn(tile[tx][r]);
        }
    }
}

// ---------------------------------------------------------------------------
// Kernel 2: C = relu(A @ W + bias), fp16 mma m16n8k16, f32 accumulate.
// 128 threads = 4 warps (2Mx2N), warp tile 64x64, BKF=64, NST=3.
// mbarrier pipeline, no per-chunk syncthreads (R13 structure, wider chunks).
// ---------------------------------------------------------------------------
__global__ __launch_bounds__(128, 2) void gemm_hmma(
    const float* __restrict__ bias, float* __restrict__ C)
{
    extern __shared__ __align__(16) __half smem[];

    const int tid = threadIdx.x;
    const int wid = tid >> 5, lane = tid & 31;
    const int g = lane >> 2, tig = lane & 3;
    const int warp_m = wid & 1, warp_n = wid >> 1;
    const int bm0 = blockIdx.y * BM, bn0 = blockIdx.x * BN;

    float acc[4][8][4];
    #pragma unroll
    for (int mt = 0; mt < 4; mt++)
        #pragma unroll
        for (int nt = 0; nt < 8; nt++)
            #pragma unroll
            for (int r = 0; r < 4; r++) acc[mt][nt][r] = 0.0f;

    const uint32_t sbase = smem_u32(smem);
    const uint32_t FULLB  = sbase + MBAR_OFF;        // 3 x 8B
    const uint32_t EMPTYB = sbase + MBAR_OFF + 32;   // 3 x 8B

    if (tid == 0) {
        #pragma unroll
        for (int s = 0; s < NST; s++) {
            mbar_init(FULLB + 8 * s, 128);   // one cp-completion arrive/thread
            mbar_init(EMPTYB + 8 * s, 4);    // one arrive per warp
        }
    }
    __syncthreads();

    // issue this thread's 16 cp16 for (stage st, chunk c)
    auto load_stage = [&](int st, int c) {
        const int k0 = c * BKF;
        uint32_t sa = sbase + (uint32_t)(st * STAGE_BYTES);
        uint32_t sb = sa + A_BYTES;
        #pragma unroll
        for (int i = 0; i < 8; i++) {
            int idx = tid + i * 128;
            int row = idx >> 3, v = idx & 7;
            cp16(sa + (uint32_t)(row * (LDAH * 2) + v * 16),
                 g_poolh + (size_t)(bm0 + row) * K_TOT + k0 + v * 8);
        }
        #pragma unroll
        for (int i = 0; i < 8; i++) {
            int idx = tid + i * 128;
            int row = idx >> 3, v = idx & 7;
            cp16(sb + (uint32_t)(row * (LDAH * 2) + v * 16),
                 g_Wth + (size_t)(bn0 + row) * K_TOT + k0 + v * 8);
        }
        cp_mbar_arrive(FULLB + 8 * st);
    };

    // prologue: stages 0..1 (chunks 0,1)
    load_stage(0, 0);
    load_stage(1, 1);

    const int q = lane >> 3, r8 = lane & 7;

    for (int c = 0; c < NC; c++) {
        const int st = c % NST;
        mbar_wait(FULLB + 8 * st, (c / NST) & 1);

        uint32_t sa = sbase + (uint32_t)(st * STAGE_BYTES);
        uint32_t sb = sa + A_BYTES;

        #pragma unroll
        for (int ks = 0; ks < 4; ks++) {
            const int k0 = ks * 16;
            uint32_t a[4][4], b[4][4];
            #pragma unroll
            for (int mt = 0; mt < 4; mt++) {
                int row = warp_m * 64 + mt * 16 + (q & 1) * 8 + r8;
                int col = k0 + (q >> 1) * 8;
                ldsm4(a[mt], sa + (uint32_t)(row * (LDAH * 2) + col * 2));
            }
            #pragma unroll
            for (int nb = 0; nb < 4; nb++) {
                int row = warp_n * 64 + nb * 16 + (q >> 1) * 8 + r8;
                int col = k0 + (q & 1) * 8;
                ldsm4(b[nb], sb + (uint32_t)(row * (LDAH * 2) + col * 2));
            }
            // after the LAST ldsm of this stage, release it for reload
            if (ks == 3 && lane == 0) mbar_arrive(EMPTYB + 8 * st);
            #pragma unroll
            for (int mt = 0; mt < 4; mt++)
                #pragma unroll
                for (int nb = 0; nb < 4; nb++) {
                    mma16816(acc[mt][2 * nb],     a[mt], b[nb][0], b[nb][1]);
                    mma16816(acc[mt][2 * nb + 1], a[mt], b[nb][2], b[nb][3]);
                }
        }

        // producer: refill stage for chunk c+2
        const int cn = c + NST - 1;
        if (cn < NC) {
            const int st2 = cn % NST;
            if (cn >= NST)   // wait for all 4 warps to release that stage
                mbar_wait(EMPTYB + 8 * st2, (cn / NST - 1) & 1);
            load_stage(st2, cn);
        }
    }

    // epilogue: bias hoisted, relu, float2 stores
    float2 bb[8];
    #pragma unroll
    for (int nt = 0; nt < 8; nt++) {
        int col = bn0 + warp_n * 64 + nt * 8 + tig * 2;
        bb[nt].x = __ldg(bias + col);
        bb[nt].y = __ldg(bias + col + 1);
    }
    #pragma unroll
    for (int mt = 0; mt < 4; mt++) {
        int r0 = bm0 + warp_m * 64 + mt * 16 + g;
        #pragma unroll
        for (int nt = 0; nt < 8; nt++) {
            int col = bn0 + warp_n * 64 + nt * 8 + tig * 2;
            float2 v0, v1;
            v0.x = fmaxf(acc[mt][nt][0] + bb[nt].x, 0.0f);
            v0.y = fmaxf(acc[mt][nt][1] + bb[nt].y, 0.0f);
            v1.x = fmaxf(acc[mt][nt][2] + bb[nt].x, 0.0f);
            v1.y = fmaxf(acc[mt][nt][3] + bb[nt].y, 0.0f);
            *(float2*)(C + (size_t)r0 * N_TOT + col) = v0;
            *(float2*)(C + (size_t)(r0 + 8) * N_TOT + col) = v1;
        }
    }
}

// ---------------------------------------------------------------------------
// Launch
// ---------------------------------------------------------------------------
extern "C" void kernel_launch(void* const* d_in, const int* in_sizes, int n_in,
                              void* d_out, int out_size)
{
    const float* h_states = (const float*)d_in[0];
    const float* end_pos  = (const float*)d_in[2];
    const float* W        = (const float*)d_in[4];
    const float* bias     = (const float*)d_in[5];
    float* out = (float*)d_out;

    static int attr_set = 0;
    if (!attr_set) {
        cudaFuncSetAttribute(gemm_hmma, cudaFuncAttributeMaxDynamicSharedMemorySize,
                             SMEM_GEMM);
        cudaFuncSetAttribute(prep_kernel, cudaFuncAttributeMaxDynamicSharedMemorySize,
                             SMEM_PREP);
        attr_set = 1;
    }

    int tr_blocks = (N_TOT / 32) * (K_TOT / 32);   // 4096
    prep_kernel<<<POOL_BLOCKS + tr_blocks, 256, SMEM_PREP>>>(h_states, end_pos, W);
    gemm_hmma<<<dim3(N_TOT / BN, M_TOT / BM), 128, SMEM_GEMM>>>(bias, out);
}

// round 17
// speedup vs baseline: 1.0801x; 1.0801x over previous
#include <cuda_runtime.h>
#include <cuda_fp16.h>
#include <cstdint>

// ---------------------------------------------------------------------------
// SocialPooling: pooled[i] = scatter-add of neighbor hidden states into an
// 8x8 grid around anchor i, then out = relu(pooled @ W + b).
// Fixed instance: S=64, P=64, B=4096, H=64, g2=64 -> K=4096, N=1024.
// Round 17: GEMM = R13 exactly (BKF=32, NST=4, mbarrier pipeline — best
// measured, 91.6us). Prep: W transpose removed — W converted fp32->fp16 in
// [K,N] layout; B fragments loaded via ldmatrix.x4.trans from K-major smem.
// ---------------------------------------------------------------------------

#define H_DIM 64
#define G2    64
#define PP    64

#define M_TOT 4096
#define N_TOT 1024
#define K_TOT 4096

#define BM 128
#define BN 128
#define BKF 32                           // fp16 k per chunk (2 k16 steps)
#define NST 4
#define NC (K_TOT / BKF)                 // 128 chunks

#define LDAH 40                          // A row stride (fp16): 80B, conflict-free
#define LDBH 136                         // B row stride (fp16): 272B, 4*row mod 32 banks
#define A_BYTES (BM * LDAH * 2)          // 10240
#define B_BYTES (BKF * LDBH * 2)         // 8704
#define STAGE_BYTES (A_BYTES + B_BYTES)  // 18944
#define MBAR_OFF (NST * STAGE_BYTES)     // 75776
#define SMEM_GEMM (MBAR_OFF + 64)

// prep kernel smem layout (pool branch)
#define PA 8
#define POOL_BLOCKS (M_TOT / PA)          // 512
#define CVT_BLOCKS 1024
#define PK_POS  16384
#define PK_HEAD 16896
#define PK_NEXT 18944
#define SMEM_PREP 20992

// scratch: fp16 pooled A (32 MB) + fp16 W [K,N] (8 MB)
__device__ __half g_poolh[(size_t)M_TOT * K_TOT];
__device__ __half g_Wh[(size_t)K_TOT * N_TOT];

// ---------------------------------------------------------------------------
// helpers
// ---------------------------------------------------------------------------
__device__ __forceinline__ uint32_t smem_u32(const void* p) {
    uint32_t a;
    asm("{ .reg .u64 t; cvta.to.shared.u64 t, %1; cvt.u32.u64 %0, t; }" : "=r"(a) : "l"(p));
    return a;
}
__device__ __forceinline__ void cp16(uint32_t dst, const void* src) {
    asm volatile("cp.async.cg.shared.global [%0], [%1], 16;" :: "r"(dst), "l"(src));
}
__device__ __forceinline__ void mbar_init(uint32_t m, uint32_t cnt) {
    asm volatile("mbarrier.init.shared.b64 [%0], %1;" :: "r"(m), "r"(cnt) : "memory");
}
__device__ __forceinline__ void cp_mbar_arrive(uint32_t m) {
    asm volatile("cp.async.mbarrier.arrive.noinc.shared.b64 [%0];" :: "r"(m) : "memory");
}
__device__ __forceinline__ void mbar_arrive(uint32_t m) {
    asm volatile("mbarrier.arrive.shared.b64 _, [%0];" :: "r"(m) : "memory");
}
__device__ __forceinline__ void mbar_wait(uint32_t m, uint32_t parity) {
    asm volatile(
        "{\n\t.reg .pred P1;\n\t"
        "LAB_%=:\n\t"
        "mbarrier.try_wait.parity.shared::cta.b64 P1, [%0], %1, 0x989680;\n\t"
        "@P1 bra.uni DONE_%=;\n\t"
        "bra.uni LAB_%=;\n\t"
        "DONE_%=:\n\t}"
        :: "r"(m), "r"(parity) : "memory");
}
__device__ __forceinline__ void ldsm4(uint32_t* r, uint32_t addr) {
    asm volatile("ldmatrix.sync.aligned.m8n8.x4.shared.b16 {%0,%1,%2,%3}, [%4];"
                 : "=r"(r[0]), "=r"(r[1]), "=r"(r[2]), "=r"(r[3]) : "r"(addr));
}
__device__ __forceinline__ void ldsm4t(uint32_t* r, uint32_t addr) {
    asm volatile("ldmatrix.sync.aligned.m8n8.x4.trans.shared.b16 {%0,%1,%2,%3}, [%4];"
                 : "=r"(r[0]), "=r"(r[1]), "=r"(r[2]), "=r"(r[3]) : "r"(addr));
}
__device__ __forceinline__ void mma16816(float* d, const uint32_t* a,
                                         uint32_t b0, uint32_t b1) {
    asm volatile(
        "mma.sync.aligned.m16n8k16.row.col.f32.f16.f16.f32 "
        "{%0,%1,%2,%3}, {%4,%5,%6,%7}, {%8,%9}, {%0,%1,%2,%3};"
        : "+f"(d[0]), "+f"(d[1]), "+f"(d[2]), "+f"(d[3])
        : "r"(a[0]), "r"(a[1]), "r"(a[2]), "r"(a[3]), "r"(b0), "r"(b1));
}

// ---------------------------------------------------------------------------
// Kernel 1 (fused prep): blocks [0,512) pool; [512, 512+1024) W fp32->fp16.
// ---------------------------------------------------------------------------
__global__ __launch_bounds__(256) void prep_kernel(
    const float* __restrict__ h_states, const float* __restrict__ end_pos,
    const float* __restrict__ W)
{
    extern __shared__ __align__(16) char sm[];
    const int tid = threadIdx.x;

    if (blockIdx.x < POOL_BLOCKS) {
        float*  sh_hidden = (float*)sm;                 // 4096 f32
        float2* sh_pos    = (float2*)(sm + PK_POS);     // 64
        int*    sh_head   = (int*)(sm + PK_HEAD);       // [PA][64]
        int*    sh_next   = (int*)(sm + PK_NEXT);       // [PA][64]

        const int blk = blockIdx.x;
        const int s  = blk >> 3;
        const int a0 = (blk & 7) * PA;

        const float4* hseq = (const float4*)(h_states + (size_t)s * PP * H_DIM);
        #pragma unroll
        for (int k = tid; k < PP * H_DIM / 4; k += 256)
            ((float4*)sh_hidden)[k] = hseq[k];
        if (tid < PP) sh_pos[tid] = ((const float2*)end_pos)[(size_t)s * PP + tid];
        #pragma unroll
        for (int k = tid; k < PA * 64; k += 256) sh_head[k] = -1;
        __syncthreads();

        #pragma unroll
        for (int idx = tid; idx < PA * 64; idx += 256) {
            int a = idx >> 6, j = idx & 63;
            int p = a0 + a;
            float px = sh_pos[p].x, py = sh_pos[p].y;
            float tlx = px - 1.0f, tly = py + 1.0f;
            float brx = px + 1.0f, bry = py - 1.0f;
            float ox = sh_pos[j].x, oy = sh_pos[j].y;
            bool oob = (ox >= brx) || (ox <= tlx) || (oy >= tly) || (oy <= bry) || (j == p);
            int cx = (int)floorf((ox - tlx) / 2.0f * 8.0f);
            int cy = (int)floorf((tly - oy) / 2.0f * 8.0f);
            int c = cx + cy * 8;
            if (!oob && c >= 0 && c < G2)
                sh_next[idx] = atomicExch(&sh_head[a * 64 + c], j);
        }
        __syncthreads();

        const int w = tid >> 5, l = tid & 31;
        const int h0 = sh_head[w * 64 + l];
        const int h1 = sh_head[w * 64 + 32 + l];
        const int* nx = sh_next + w * 64;
        const float2* hid2 = (const float2*)sh_hidden;
        uint32_t* dst = (uint32_t*)(g_poolh + (size_t)(s * PP + a0 + w) * (G2 * H_DIM));
        #pragma unroll
        for (int c = 0; c < G2; c++) {
            int j = __shfl_sync(0xffffffffu, (c < 32) ? h0 : h1, c & 31);
            uint32_t u = 0u;
            if (j >= 0) {
                float2 acc = hid2[j * 32 + l];
                j = nx[j];
                while (j >= 0) {
                    float2 v = hid2[j * 32 + l];
                    acc.x += v.x; acc.y += v.y;
                    j = nx[j];
                }
                __half2 h = __floats2half2_rn(acc.x, acc.y);
                u = *reinterpret_cast<uint32_t*>(&h);
            }
            dst[c * 32 + l] = u;
        }
    } else {
        // W [K,N] fp32 -> fp16, same layout, coalesced grid-stride convert
        const int bid = blockIdx.x - POOL_BLOCKS;
        const float4* src = (const float4*)W;
        uint2* dst = (uint2*)g_Wh;
        const int n4 = (K_TOT * N_TOT) / 4;     // 1M float4
        for (int i = bid * 256 + tid; i < n4; i += CVT_BLOCKS * 256) {
            float4 v = src[i];
            __half2 h0 = __floats2half2_rn(v.x, v.y);
            __half2 h1 = __floats2half2_rn(v.z, v.w);
            uint2 u;
            u.x = *reinterpret_cast<uint32_t*>(&h0);
            u.y = *reinterpret_cast<uint32_t*>(&h1);
            dst[i] = u;
        }
    }
}

// ---------------------------------------------------------------------------
// Kernel 2: C = relu(A @ W + bias), fp16 mma m16n8k16, f32 accumulate.
// 128 threads = 4 warps (2Mx2N), warp tile 64x64, BKF=32, NST=4.
// mbarrier pipeline (R13). A: [M,K] non-trans ldsm; B: [K,N] trans ldsm.
// ---------------------------------------------------------------------------
__global__ __launch_bounds__(128, 2) void gemm_hmma(
    const float* __restrict__ bias, float* __restrict__ C)
{
    extern __shared__ __align__(16) __half smem[];

    const int tid = threadIdx.x;
    const int wid = tid >> 5, lane = tid & 31;
    const int g = lane >> 2, tig = lane & 3;
    const int warp_m = wid & 1, warp_n = wid >> 1;
    const int bm0 = blockIdx.y * BM, bn0 = blockIdx.x * BN;

    float acc[4][8][4];
    #pragma unroll
    for (int mt = 0; mt < 4; mt++)
        #pragma unroll
        for (int nt = 0; nt < 8; nt++)
            #pragma unroll
            for (int r = 0; r < 4; r++) acc[mt][nt][r] = 0.0f;

    const uint32_t sbase = smem_u32(smem);
    const uint32_t FULLB  = sbase + MBAR_OFF;        // 4 x 8B
    const uint32_t EMPTYB = sbase + MBAR_OFF + 32;   // 4 x 8B

    if (tid == 0) {
        #pragma unroll
        for (int s = 0; s < NST; s++) {
            mbar_init(FULLB + 8 * s, 128);   // one cp-completion arrive/thread
            mbar_init(EMPTYB + 8 * s, 4);    // one arrive per warp
        }
    }
    __syncthreads();

    // issue this thread's 8 cp16 for (stage st, chunk c)
    // A tile: 128 rows x 32 fp16 (4 x 16B per row) -> 512 cp16
    // B tile: 32 k-rows x 128 n (16 x 16B per row) -> 512 cp16
    auto load_stage = [&](int st, int c) {
        const int k0 = c * BKF;
        uint32_t sa = sbase + (uint32_t)(st * STAGE_BYTES);
        uint32_t sb = sa + A_BYTES;
        #pragma unroll
        for (int i = 0; i < 4; i++) {
            int idx = tid + i * 128;
            int row = idx >> 2, v = idx & 3;
            cp16(sa + (uint32_t)(row * (LDAH * 2) + v * 16),
                 g_poolh + (size_t)(bm0 + row) * K_TOT + k0 + v * 8);
        }
        #pragma unroll
        for (int i = 0; i < 4; i++) {
            int idx = tid + i * 128;
            int row = idx >> 4, v = idx & 15;   // 32 rows x 16 vec
            cp16(sb + (uint32_t)(row * (LDBH * 2) + v * 16),
                 g_Wh + (size_t)(k0 + row) * N_TOT + bn0 + v * 8);
        }
        cp_mbar_arrive(FULLB + 8 * st);
    };

    // prologue: stages 0..2
    load_stage(0, 0);
    load_stage(1, 1);
    load_stage(2, 2);

    const int q = lane >> 3, r8 = lane & 7;

    for (int c = 0; c < NC; c++) {
        const int st = c & (NST - 1);
        mbar_wait(FULLB + 8 * st, (c >> 2) & 1);

        uint32_t sa = sbase + (uint32_t)(st * STAGE_BYTES);
        uint32_t sb = sa + A_BYTES;

        #pragma unroll
        for (int ks = 0; ks < 2; ks++) {
            const int k0 = ks * 16;
            uint32_t a[4][4], b[4][4];
            #pragma unroll
            for (int mt = 0; mt < 4; mt++) {
                int row = warp_m * 64 + mt * 16 + (q & 1) * 8 + r8;
                int col = k0 + (q >> 1) * 8;
                ldsm4(a[mt], sa + (uint32_t)(row * (LDAH * 2) + col * 2));
            }
            #pragma unroll
            for (int nb = 0; nb < 4; nb++) {
                // trans load from K-major B: (k-row, n-col) swapped vs old path
                int krow = k0 + (q & 1) * 8 + r8;
                int ncol = warp_n * 64 + nb * 16 + (q >> 1) * 8;
                ldsm4t(b[nb], sb + (uint32_t)(krow * (LDBH * 2) + ncol * 2));
            }
            // after the LAST ldsm of this stage, release it for reload
            if (ks == 1 && lane == 0) mbar_arrive(EMPTYB + 8 * st);
            #pragma unroll
            for (int mt = 0; mt < 4; mt++)
                #pragma unroll
                for (int nb = 0; nb < 4; nb++) {
                    mma16816(acc[mt][2 * nb],     a[mt], b[nb][0], b[nb][1]);
                    mma16816(acc[mt][2 * nb + 1], a[mt], b[nb][2], b[nb][3]);
                }
        }

        // producer: refill stage for chunk c+3
        const int cn = c + NST - 1;
        if (cn < NC) {
            const int st2 = cn & (NST - 1);
            if (cn >= NST)   // wait for all 4 warps to release that stage
                mbar_wait(EMPTYB + 8 * st2, ((cn >> 2) + 1) & 1);
            load_stage(st2, cn);
        }
    }

    // epilogue: bias hoisted, relu, float2 stores
    float2 bb[8];
    #pragma unroll
    for (int nt = 0; nt < 8; nt++) {
        int col = bn0 + warp_n * 64 + nt * 8 + tig * 2;
        bb[nt].x = __ldg(bias + col);
        bb[nt].y = __ldg(bias + col + 1);
    }
    #pragma unroll
    for (int mt = 0; mt < 4; mt++) {
        int r0 = bm0 + warp_m * 64 + mt * 16 + g;
        #pragma unroll
        for (int nt = 0; nt < 8; nt++) {
            int col = bn0 + warp_n * 64 + nt * 8 + tig * 2;
            float2 v0, v1;
            v0.x = fmaxf(acc[mt][nt][0] + bb[nt].x, 0.0f);
            v0.y = fmaxf(acc[mt][nt][1] + bb[nt].y, 0.0f);
            v1.x = fmaxf(acc[mt][nt][2] + bb[nt].x, 0.0f);
            v1.y = fmaxf(acc[mt][nt][3] + bb[nt].y, 0.0f);
            *(float2*)(C + (size_t)r0 * N_TOT + col) = v0;
            *(float2*)(C + (size_t)(r0 + 8) * N_TOT + col) = v1;
        }
    }
}

// ---------------------------------------------------------------------------
// Launch
// ---------------------------------------------------------------------------
extern "C" void kernel_launch(void* const* d_in, const int* in_sizes, int n_in,
                              void* d_out, int out_size)
{
    const float* h_states = (const float*)d_in[0];
    const float* end_pos  = (const float*)d_in[2];
    const float* W        = (const float*)d_in[4];
    const float* bias     = (const float*)d_in[5];
    float* out = (float*)d_out;

    static int attr_set = 0;
    if (!attr_set) {
        cudaFuncSetAttribute(gemm_hmma, cudaFuncAttributeMaxDynamicSharedMemorySize,
                             SMEM_GEMM);
        cudaFuncSetAttribute(prep_kernel, cudaFuncAttributeMaxDynamicSharedMemorySize,
                             SMEM_PREP);
        attr_set = 1;
    }

    prep_kernel<<<POOL_BLOCKS + CVT_BLOCKS, 256, SMEM_PREP>>>(h_states, end_pos, W);
    gemm_hmma<<<dim3(N_TOT / BN, M_TOT / BM), 128, SMEM_GEMM>>>(bias, out);
}